// round 1
// baseline (speedup 1.0000x reference)
#include <cuda_runtime.h>

#define Bn 8
#define Nn 1024
#define En 256
#define Hn 8
#define Dn 32
#define Cn 4

// ---- scratch (static device globals; allocation-free per harness rules) ----
__device__ float d_Q[Bn * Hn * Nn * Dn];    // 8 MB
__device__ float d_K[Bn * Hn * Nn * Dn];    // 8 MB
__device__ float d_V[Bn * Hn * Nn * Dn];    // 8 MB
__device__ float d_ctx[Bn * Hn * Nn * Dn];  // 8 MB

// ============================================================================
// Kernel 1: QKV projection GEMM.  C = X @ W + b, written in [B,H,N,D] layout.
// M = B*N = 8192, Ncols = 256, K = 256.  gridDim.z selects Q/K/V.
// 64x64 tile, BK=16, 256 threads, 4x4 per thread.
// ============================================================================
#define BM 64
#define BN 64
#define BK 16

__global__ __launch_bounds__(256)
void gemm_qkv(const float* __restrict__ X,
              const float* __restrict__ Wq, const float* __restrict__ bq,
              const float* __restrict__ Wk, const float* __restrict__ bk,
              const float* __restrict__ Wv, const float* __restrict__ bv)
{
    __shared__ float As[BK][BM + 4];   // [k][m], +4 pad (16B-aligned rows)
    __shared__ float Bs[BK][BN];       // [k][n]

    const int z = blockIdx.z;
    const float* __restrict__ W    = (z == 0) ? Wq : (z == 1) ? Wk : Wv;
    const float* __restrict__ bias = (z == 0) ? bq : (z == 1) ? bk : bv;
    float* __restrict__ Out        = (z == 0) ? d_Q : (z == 1) ? d_K : d_V;

    const int tid  = threadIdx.x;
    const int row0 = blockIdx.y * BM;
    const int col0 = blockIdx.x * BN;
    const int tx = tid & 15;
    const int ty = tid >> 4;

    const int a_m = tid >> 2;          // 0..63
    const int a_k = (tid & 3) * 4;     // 0,4,8,12
    const int b_k = tid >> 4;          // 0..15
    const int b_n = (tid & 15) * 4;    // 0..60

    float acc[4][4] = {};

    for (int k0 = 0; k0 < En; k0 += BK) {
        float4 av = *(const float4*)&X[(row0 + a_m) * En + k0 + a_k];
        As[a_k + 0][a_m] = av.x;
        As[a_k + 1][a_m] = av.y;
        As[a_k + 2][a_m] = av.z;
        As[a_k + 3][a_m] = av.w;
        *(float4*)&Bs[b_k][b_n] = *(const float4*)&W[(k0 + b_k) * En + col0 + b_n];
        __syncthreads();
#pragma unroll
        for (int k = 0; k < BK; k++) {
            float4 a4 = *(const float4*)&As[k][ty * 4];
            float4 b4 = *(const float4*)&Bs[k][tx * 4];
            acc[0][0] += a4.x * b4.x; acc[0][1] += a4.x * b4.y; acc[0][2] += a4.x * b4.z; acc[0][3] += a4.x * b4.w;
            acc[1][0] += a4.y * b4.x; acc[1][1] += a4.y * b4.y; acc[1][2] += a4.y * b4.z; acc[1][3] += a4.y * b4.w;
            acc[2][0] += a4.z * b4.x; acc[2][1] += a4.z * b4.y; acc[2][2] += a4.z * b4.z; acc[2][3] += a4.z * b4.w;
            acc[3][0] += a4.w * b4.x; acc[3][1] += a4.w * b4.y; acc[3][2] += a4.w * b4.z; acc[3][3] += a4.w * b4.w;
        }
        __syncthreads();
    }

    const int c  = col0 + tx * 4;     // aligned 4, within one 32-wide head
    const int h  = c >> 5;
    const int dd = c & 31;
    float4 bz = *(const float4*)&bias[c];
#pragma unroll
    for (int i = 0; i < 4; i++) {
        int m = row0 + ty * 4 + i;
        int b = m >> 10, n = m & 1023;
        float4 o;
        o.x = acc[i][0] + bz.x;
        o.y = acc[i][1] + bz.y;
        o.z = acc[i][2] + bz.z;
        o.w = acc[i][3] + bz.w;
        *(float4*)&Out[((b * Hn + h) * Nn + n) * Dn + dd] = o;
    }
}

// ============================================================================
// Kernel 2: fused adjacency-bias flash attention.
// Block = (b, 32-row tile); thread (tid) = (head h = tid/32, row i = tid%32).
// Streams over 16-wide column tiles; adj read exactly ONCE (all heads share it).
// Online softmax per thread (thread owns its full row).
// ============================================================================
#define TM 32
#define TJ 16

__global__ __launch_bounds__(256)
void attn_kernel(const float* __restrict__ adj,
                 const float* __restrict__ Wa,
                 const float* __restrict__ ba)
{
    __shared__ float Ks[Hn][TJ][Dn];        // 16 KB
    __shared__ float Vs[Hn][TJ][Dn];        // 16 KB
    __shared__ float Adjs[TJ][Cn][TM];      // 8 KB, [j][c][i] -> conflict-free reads

    const int tid  = threadIdx.x;
    const int h    = tid >> 5;
    const int i    = tid & 31;
    const int bIdx = blockIdx.x >> 5;       // 32 row tiles per batch
    const int tile = blockIdx.x & 31;
    const int row  = tile * TM + i;

    float q[Dn];
    {
        const float4* qp = (const float4*)&d_Q[((bIdx * Hn + h) * Nn + row) * Dn];
#pragma unroll
        for (int d4 = 0; d4 < Dn / 4; d4++) {
            float4 v = qp[d4];
            q[d4 * 4 + 0] = v.x; q[d4 * 4 + 1] = v.y;
            q[d4 * 4 + 2] = v.z; q[d4 * 4 + 3] = v.w;
        }
    }
    float wa[Cn];
#pragma unroll
    for (int c = 0; c < Cn; c++) wa[c] = Wa[c * Hn + h];
    const float bah = ba[h];

    float mrun = -1e30f, l = 0.f;
    float acc[Dn] = {};
    const float scale = 0.17677669529663687f;  // 1/sqrt(32)

    for (int j0 = 0; j0 < Nn; j0 += TJ) {
        // ---- stage K,V tiles: 8*16*32 floats each = 1024 float4, 4/thread ----
#pragma unroll
        for (int u = 0; u < 4; u++) {
            int idx = tid + u * 256;           // 0..1023
            int hh  = idx >> 7;                // /128
            int rr  = idx & 127;
            int jj  = rr >> 3;                 // /8
            int dd  = (rr & 7) * 4;
            long goff = (long)((bIdx * Hn + hh) * Nn + j0 + jj) * Dn + dd;
            *(float4*)&Ks[hh][jj][dd] = *(const float4*)&d_K[goff];
            *(float4*)&Vs[hh][jj][dd] = *(const float4*)&d_V[goff];
        }
        // ---- stage adj tile [32 rows][16 cols][4 ch] -> Adjs[j][c][i] ----
#pragma unroll
        for (int u = 0; u < 2; u++) {
            int idx = tid + u * 256;           // 0..511
            int ii  = idx >> 4;
            int jj  = idx & 15;
            float4 a4 = *(const float4*)&adj[((long)(bIdx * Nn + tile * TM + ii) * Nn + (j0 + jj)) * Cn];
            Adjs[jj][0][ii] = a4.x;
            Adjs[jj][1][ii] = a4.y;
            Adjs[jj][2][ii] = a4.z;
            Adjs[jj][3][ii] = a4.w;
        }
        __syncthreads();

        float s[TJ];
        float tmax = -1e30f;
#pragma unroll
        for (int j = 0; j < TJ; j++) {
            float sv = 0.f;
            const float4* kp = (const float4*)&Ks[h][j][0];
#pragma unroll
            for (int d4 = 0; d4 < Dn / 4; d4++) {
                float4 k4 = kp[d4];
                sv += q[d4 * 4 + 0] * k4.x + q[d4 * 4 + 1] * k4.y
                    + q[d4 * 4 + 2] * k4.z + q[d4 * 4 + 3] * k4.w;
            }
            float bv = bah;
#pragma unroll
            for (int c = 0; c < Cn; c++) bv += Adjs[j][c][i] * wa[c];
            sv = sv * scale + bv;
            s[j] = sv;
            tmax = fmaxf(tmax, sv);
        }

        float mnew = fmaxf(mrun, tmax);
        float corr = __expf(mrun - mnew);
        l *= corr;
#pragma unroll
        for (int d = 0; d < Dn; d++) acc[d] *= corr;

#pragma unroll
        for (int j = 0; j < TJ; j++) {
            float p = __expf(s[j] - mnew);
            l += p;
            const float4* vp = (const float4*)&Vs[h][j][0];
#pragma unroll
            for (int d4 = 0; d4 < Dn / 4; d4++) {
                float4 v4 = vp[d4];
                acc[d4 * 4 + 0] += p * v4.x;
                acc[d4 * 4 + 1] += p * v4.y;
                acc[d4 * 4 + 2] += p * v4.z;
                acc[d4 * 4 + 3] += p * v4.w;
            }
        }
        mrun = mnew;
        __syncthreads();
    }

    const float inv = 1.f / l;
    float4* op = (float4*)&d_ctx[((bIdx * Hn + h) * Nn + row) * Dn];
#pragma unroll
    for (int d4 = 0; d4 < Dn / 4; d4++) {
        float4 o;
        o.x = acc[d4 * 4 + 0] * inv;
        o.y = acc[d4 * 4 + 1] * inv;
        o.z = acc[d4 * 4 + 2] * inv;
        o.w = acc[d4 * 4 + 3] * inv;
        op[d4] = o;
    }
}

// ============================================================================
// Kernel 3: output projection + residual.
// Out[b,n,:] = ctx_reshaped[b,n,:] @ Wo + bo + x[b,n,:]
// ctx gathered from [B,H,N,D] head layout.
// ============================================================================
__global__ __launch_bounds__(256)
void gemm_out(const float* __restrict__ X,
              const float* __restrict__ Wo, const float* __restrict__ bo,
              float* __restrict__ Out)
{
    __shared__ float As[BK][BM + 4];
    __shared__ float Bs[BK][BN];

    const int tid  = threadIdx.x;
    const int row0 = blockIdx.y * BM;
    const int col0 = blockIdx.x * BN;
    const int tx = tid & 15;
    const int ty = tid >> 4;

    const int a_m = tid >> 2;
    const int a_k = (tid & 3) * 4;
    const int b_k = tid >> 4;
    const int b_n = (tid & 15) * 4;

    const int am_g = row0 + a_m;
    const int am_b = am_g >> 10, am_n = am_g & 1023;

    float acc[4][4] = {};

    for (int k0 = 0; k0 < En; k0 += BK) {
        int k  = k0 + a_k;
        int hh = k >> 5, dd = k & 31;   // float4 stays within one head row
        float4 av = *(const float4*)&d_ctx[((am_b * Hn + hh) * Nn + am_n) * Dn + dd];
        As[a_k + 0][a_m] = av.x;
        As[a_k + 1][a_m] = av.y;
        As[a_k + 2][a_m] = av.z;
        As[a_k + 3][a_m] = av.w;
        *(float4*)&Bs[b_k][b_n] = *(const float4*)&Wo[(k0 + b_k) * En + col0 + b_n];
        __syncthreads();
#pragma unroll
        for (int kk = 0; kk < BK; kk++) {
            float4 a4 = *(const float4*)&As[kk][ty * 4];
            float4 b4 = *(const float4*)&Bs[kk][tx * 4];
            acc[0][0] += a4.x * b4.x; acc[0][1] += a4.x * b4.y; acc[0][2] += a4.x * b4.z; acc[0][3] += a4.x * b4.w;
            acc[1][0] += a4.y * b4.x; acc[1][1] += a4.y * b4.y; acc[1][2] += a4.y * b4.z; acc[1][3] += a4.y * b4.w;
            acc[2][0] += a4.z * b4.x; acc[2][1] += a4.z * b4.y; acc[2][2] += a4.z * b4.z; acc[2][3] += a4.z * b4.w;
            acc[3][0] += a4.w * b4.x; acc[3][1] += a4.w * b4.y; acc[3][2] += a4.w * b4.z; acc[3][3] += a4.w * b4.w;
        }
        __syncthreads();
    }

    const int c = col0 + tx * 4;
    float4 bz = *(const float4*)&bo[c];
#pragma unroll
    for (int i = 0; i < 4; i++) {
        int m = row0 + ty * 4 + i;
        float4 xr = *(const float4*)&X[m * En + c];
        float4 o;
        o.x = acc[i][0] + bz.x + xr.x;
        o.y = acc[i][1] + bz.y + xr.y;
        o.z = acc[i][2] + bz.z + xr.z;
        o.w = acc[i][3] + bz.w + xr.w;
        *(float4*)&Out[m * En + c] = o;
    }
}

// ============================================================================
extern "C" void kernel_launch(void* const* d_in, const int* in_sizes, int n_in,
                              void* d_out, int out_size)
{
    const float* x   = (const float*)d_in[0];
    const float* adj = (const float*)d_in[1];
    const float* Wq  = (const float*)d_in[2];
    const float* bq  = (const float*)d_in[3];
    const float* Wk  = (const float*)d_in[4];
    const float* bk  = (const float*)d_in[5];
    const float* Wv  = (const float*)d_in[6];
    const float* bv  = (const float*)d_in[7];
    const float* Wo  = (const float*)d_in[8];
    const float* bo  = (const float*)d_in[9];
    const float* Wa  = (const float*)d_in[10];
    const float* ba  = (const float*)d_in[11];
    float* out = (float*)d_out;

    // 1) QKV projections (one launch, z = Q/K/V)
    dim3 gq(En / BN, (Bn * Nn) / BM, 3);       // (4, 128, 3)
    gemm_qkv<<<gq, 256>>>(x, Wq, bq, Wk, bk, Wv, bv);

    // 2) fused bias + flash attention
    attn_kernel<<<Bn * (Nn / TM), 256>>>(adj, Wa, ba);

    // 3) output projection + residual
    dim3 go(En / BN, (Bn * Nn) / BM);          // (4, 128)
    gemm_out<<<go, 256>>>(x, Wo, bo, out);
}